// round 4
// baseline (speedup 1.0000x reference)
#include <cuda_runtime.h>
#include <cstdint>

// LIF spike scan. x: [64, 8192, 100] fp32 (T contiguous) -> spikes (same shape).
//   mem = mem*TAU + x_t - w ; spike = (mem > THRESH)
//   w = BETA*w + (1-BETA)*(A*mem + B*spike) ; mem -= spike*THRESH
//
// R4: persistent CTAs + double-buffered TMA bulk pipeline. While computing
// tile k (buffer b), the load of tile k+1 (buffer 1-b) is already in flight;
// the store of tile k-1 is drained with wait_group 0 before reusing buffer 1-b.

#define TAU    0.5f
#define THRESH 0.5f
#define BETA   0.9f
#define C_MS   0.05f   // (1-BETA)*A == (1-BETA)*B == 0.05

constexpr int T_LEN       = 100;
constexpr int ROWS        = 128;                 // rows/tile == threads/CTA
constexpr int TILE_FLOATS = ROWS * T_LEN;        // 12800
constexpr int TILE_BYTES  = TILE_FLOATS * 4;     // 51200
constexpr int DATA_OFF    = 32;                  // bytes: 2 mbarrier slots
constexpr int SMEM_BYTES  = DATA_OFF + 2 * TILE_BYTES;   // 102,432
constexpr int GRID        = 304;                 // 2 CTAs/SM

__device__ __forceinline__ void lif_step(float xt, float& mem, float& w, float& sp) {
    mem = fmaf(mem, TAU, xt) - w;
    sp  = (mem > THRESH) ? 1.0f : 0.0f;
    w   = fmaf(BETA, w, fmaf(C_MS, mem, C_MS * sp));
    mem = fmaf(-sp, THRESH, mem);
}

__device__ __forceinline__ void mbar_wait_acq(uint32_t mbar, uint32_t phase) {
    uint32_t done;
    asm volatile(
        "{\n\t.reg .pred p;\n\t"
        "mbarrier.try_wait.parity.acquire.cta.shared::cta.b64 p, [%1], %2;\n\t"
        "selp.b32 %0, 1, 0, p;\n\t}"
        : "=r"(done) : "r"(mbar), "r"(phase) : "memory");
    if (!done) {
        asm volatile(
            "{\n\t.reg .pred P1;\n\t"
            "WL_%=:\n\t"
            "mbarrier.try_wait.parity.acquire.cta.shared::cta.b64 P1, [%0], %1, 0x989680;\n\t"
            "@P1 bra.uni WD_%=;\n\t"
            "bra.uni WL_%=;\n\t"
            "WD_%=:\n\t}"
            :: "r"(mbar), "r"(phase) : "memory");
    }
}

__global__ __launch_bounds__(ROWS, 2) void lif_kernel(const float* __restrict__ x,
                                                      float* __restrict__ out,
                                                      int n_tiles) {
    extern __shared__ float smem[];
    const int tid = threadIdx.x;

    uint32_t sb;
    asm("{ .reg .u64 t; cvta.to.shared.u64 t, %1; cvt.u32.u64 %0, t; }"
        : "=r"(sb) : "l"(smem));
    const uint32_t mbar0 = sb;
    const uint32_t mbar1 = sb + 16;
    const uint32_t dsh0  = sb + DATA_OFF;
    const uint32_t dsh1  = sb + DATA_OFF + TILE_BYTES;
    float* buf0 = smem + DATA_OFF / 4;
    float* buf1 = buf0 + TILE_FLOATS;

    if (tid == 0) {
        asm volatile("mbarrier.init.shared.b64 [%0], 1;" :: "r"(mbar0) : "memory");
        asm volatile("mbarrier.init.shared.b64 [%0], 1;" :: "r"(mbar1) : "memory");
    }
    __syncthreads();

    const int G = gridDim.x;

    // Prologue: load first tile into buffer 0.
    if (tid == 0 && (int)blockIdx.x < n_tiles) {
        asm volatile("mbarrier.arrive.expect_tx.shared.b64 _, [%0], %1;"
                     :: "r"(mbar0), "r"((uint32_t)TILE_BYTES) : "memory");
        asm volatile("cp.async.bulk.shared::cta.global.mbarrier::complete_tx::bytes "
                     "[%0], [%1], %2, [%3];"
                     :: "r"(dsh0), "l"(x + (size_t)blockIdx.x * TILE_FLOATS),
                        "r"((uint32_t)TILE_BYTES), "r"(mbar0) : "memory");
    }

    uint32_t ph0 = 0, ph1 = 0;
    int k = 0;
    for (int t = blockIdx.x; t < n_tiles; t += G, k++) {
        const int b = k & 1;
        const uint32_t mbar_cur = b ? mbar1 : mbar0;
        const uint32_t mbar_nxt = b ? mbar0 : mbar1;
        const uint32_t dsh_nxt  = b ? dsh0 : dsh1;
        float* buf_cur = b ? buf1 : buf0;

        // Issue load of next tile into the other buffer (after draining the
        // async store that last read from it).
        const int tn = t + G;
        if (tid == 0 && tn < n_tiles) {
            if (k >= 1)
                asm volatile("cp.async.bulk.wait_group 0;" ::: "memory");
            asm volatile("mbarrier.arrive.expect_tx.shared.b64 _, [%0], %1;"
                         :: "r"(mbar_nxt), "r"((uint32_t)TILE_BYTES) : "memory");
            asm volatile("cp.async.bulk.shared::cta.global.mbarrier::complete_tx::bytes "
                         "[%0], [%1], %2, [%3];"
                         :: "r"(dsh_nxt), "l"(x + (size_t)tn * TILE_FLOATS),
                            "r"((uint32_t)TILE_BYTES), "r"(mbar_nxt) : "memory");
        }

        // Wait for tile t's load.
        if (b) { mbar_wait_acq(mbar1, ph1); ph1 ^= 1; }
        else   { mbar_wait_acq(mbar0, ph0); ph0 ^= 1; }

        // Scan: one thread per row; float4 smem, bank-conflict-free (100%32==4).
        {
            float4* srow = reinterpret_cast<float4*>(buf_cur + tid * T_LEN);
            float mem = 0.0f, w = 0.0f;
            #pragma unroll
            for (int j = 0; j < T_LEN / 4; j++) {
                float4 v = srow[j];
                float4 sp;
                lif_step(v.x, mem, w, sp.x);
                lif_step(v.y, mem, w, sp.y);
                lif_step(v.z, mem, w, sp.z);
                lif_step(v.w, mem, w, sp.w);
                srow[j] = sp;
            }
        }
        __syncthreads();

        // Async bulk store of tile t's spikes.
        if (tid == 0) {
            asm volatile("fence.proxy.async.shared::cta;" ::: "memory");
            asm volatile("cp.async.bulk.global.shared::cta.bulk_group [%0], [%1], %2;"
                         :: "l"(out + (size_t)t * TILE_FLOATS),
                            "r"(b ? dsh1 : dsh0), "r"((uint32_t)TILE_BYTES) : "memory");
            asm volatile("cp.async.bulk.commit_group;" ::: "memory");
        }
    }

    if (tid == 0)
        asm volatile("cp.async.bulk.wait_group 0;" ::: "memory");
}

extern "C" void kernel_launch(void* const* d_in, const int* in_sizes, int n_in,
                              void* d_out, int out_size) {
    const float* x = (const float*)d_in[0];
    float* out = (float*)d_out;
    int n_tiles = in_sizes[0] / TILE_FLOATS;   // 4096

    int grid = GRID < n_tiles ? GRID : n_tiles;
    cudaFuncSetAttribute(lif_kernel, cudaFuncAttributeMaxDynamicSharedMemorySize,
                         SMEM_BYTES);
    lif_kernel<<<grid, ROWS, SMEM_BYTES>>>(x, out, n_tiles);
}

// round 5
// speedup vs baseline: 1.0075x; 1.0075x over previous
#include <cuda_runtime.h>
#include <cstdint>

// LIF spike scan. x: [64, 8192, 100] fp32 (T contiguous) -> spikes (same shape).
//   mem = mem*TAU + x_t - w ; spike = (mem > THRESH)
//   w = BETA*w + (1-BETA)*(A*mem + B*spike) ; mem -= spike*THRESH
//
// R5: persistent 1 CTA/SM, 4-deep TMA ring (loads 3 tiles ahead).
// Buffer reuse gated on cp.async.bulk.wait_group.read 1: waits only for the
// smem-read phase of the older store, never on the just-committed one.

#define TAU    0.5f
#define THRESH 0.5f
#define BETA   0.9f
#define C_MS   0.05f   // (1-BETA)*A == (1-BETA)*B

constexpr int T_LEN       = 100;
constexpr int ROWS        = 128;                 // rows/tile == threads/CTA
constexpr int TILE_FLOATS = ROWS * T_LEN;        // 12800
constexpr int TILE_BYTES  = TILE_FLOATS * 4;     // 51200
constexpr int NBUF        = 4;
constexpr int DATA_OFF    = 64;                  // 4 mbarrier slots (16B each)
constexpr int SMEM_BYTES  = DATA_OFF + NBUF * TILE_BYTES;   // 204,864
constexpr int GRID        = 152;                 // 1 CTA/SM

__device__ __forceinline__ void lif_step(float xt, float& mem, float& w, float& sp) {
    mem = fmaf(mem, TAU, xt) - w;
    sp  = (mem > THRESH) ? 1.0f : 0.0f;
    w   = fmaf(BETA, w, fmaf(C_MS, mem, C_MS * sp));
    mem = fmaf(-sp, THRESH, mem);
}

__device__ __forceinline__ void mbar_wait_acq(uint32_t mbar, uint32_t phase) {
    uint32_t done;
    asm volatile(
        "{\n\t.reg .pred p;\n\t"
        "mbarrier.try_wait.parity.acquire.cta.shared::cta.b64 p, [%1], %2;\n\t"
        "selp.b32 %0, 1, 0, p;\n\t}"
        : "=r"(done) : "r"(mbar), "r"(phase) : "memory");
    if (!done) {
        asm volatile(
            "{\n\t.reg .pred P1;\n\t"
            "WL_%=:\n\t"
            "mbarrier.try_wait.parity.acquire.cta.shared::cta.b64 P1, [%0], %1, 0x989680;\n\t"
            "@P1 bra.uni WD_%=;\n\t"
            "bra.uni WL_%=;\n\t"
            "WD_%=:\n\t}"
            :: "r"(mbar), "r"(phase) : "memory");
    }
}

__device__ __forceinline__ void tma_load(uint32_t dsh, const float* g, uint32_t mbar) {
    asm volatile("mbarrier.arrive.expect_tx.shared.b64 _, [%0], %1;"
                 :: "r"(mbar), "r"((uint32_t)TILE_BYTES) : "memory");
    asm volatile("cp.async.bulk.shared::cta.global.mbarrier::complete_tx::bytes "
                 "[%0], [%1], %2, [%3];"
                 :: "r"(dsh), "l"(g), "r"((uint32_t)TILE_BYTES), "r"(mbar) : "memory");
}

__global__ __launch_bounds__(ROWS, 1) void lif_kernel(const float* __restrict__ x,
                                                      float* __restrict__ out,
                                                      int n_tiles) {
    extern __shared__ float smem[];
    const int tid = threadIdx.x;

    uint32_t sb;
    asm("{ .reg .u64 t; cvta.to.shared.u64 t, %1; cvt.u32.u64 %0, t; }"
        : "=r"(sb) : "l"(smem));

    if (tid == 0) {
        #pragma unroll
        for (int b = 0; b < NBUF; b++)
            asm volatile("mbarrier.init.shared.b64 [%0], 1;"
                         :: "r"(sb + 16u * b) : "memory");
    }
    __syncthreads();

    const int G = gridDim.x;

    // Prologue: issue loads for the first NBUF-1 tiles of this CTA.
    if (tid == 0) {
        #pragma unroll
        for (int p = 0; p < NBUF - 1; p++) {
            int t = blockIdx.x + p * G;
            if (t < n_tiles)
                tma_load(sb + DATA_OFF + (uint32_t)p * TILE_BYTES,
                         x + (size_t)t * TILE_FLOATS, sb + 16u * p);
        }
    }

    uint32_t phases = 0;   // bit b = expected parity for buffer b
    int k = 0;
    for (int t = blockIdx.x; t < n_tiles; t += G, k++) {
        const int b = k & (NBUF - 1);
        const uint32_t mbar = sb + 16u * b;
        const uint32_t dsh  = sb + DATA_OFF + (uint32_t)b * TILE_BYTES;
        float* buf = smem + DATA_OFF / 4 + b * TILE_FLOATS;

        // Wait tile t loaded.
        mbar_wait_acq(mbar, (phases >> b) & 1u);
        phases ^= (1u << b);

        // Scan: one thread per row; float4 smem, bank-conflict-free (100%32==4).
        {
            float4* srow = reinterpret_cast<float4*>(buf + tid * T_LEN);
            float mem = 0.0f, w = 0.0f;
            #pragma unroll
            for (int j = 0; j < T_LEN / 4; j++) {
                float4 v = srow[j];
                float4 sp;
                lif_step(v.x, mem, w, sp.x);
                lif_step(v.y, mem, w, sp.y);
                lif_step(v.z, mem, w, sp.z);
                lif_step(v.w, mem, w, sp.w);
                srow[j] = sp;
            }
        }
        __syncthreads();

        if (tid == 0) {
            // Store tile t's spikes (async, one bulk group per tile).
            asm volatile("fence.proxy.async.shared::cta;" ::: "memory");
            asm volatile("cp.async.bulk.global.shared::cta.bulk_group [%0], [%1], %2;"
                         :: "l"(out + (size_t)t * TILE_FLOATS), "r"(dsh),
                            "r"((uint32_t)TILE_BYTES) : "memory");
            asm volatile("cp.async.bulk.commit_group;" ::: "memory");

            // Issue load for tile k+NBUF-1 into buffer (k+3)&3, last read by
            // store k-1. wait_group.read 1 => store k-1's smem reads done,
            // store k may remain fully outstanding.
            const int tn = t + (NBUF - 1) * G;
            if (tn < n_tiles) {
                asm volatile("cp.async.bulk.wait_group.read 1;" ::: "memory");
                const int bn = (k + NBUF - 1) & (NBUF - 1);
                tma_load(sb + DATA_OFF + (uint32_t)bn * TILE_BYTES,
                         x + (size_t)tn * TILE_FLOATS, sb + 16u * bn);
            }
        }
    }

    if (tid == 0)
        asm volatile("cp.async.bulk.wait_group 0;" ::: "memory");
}

extern "C" void kernel_launch(void* const* d_in, const int* in_sizes, int n_in,
                              void* d_out, int out_size) {
    const float* x = (const float*)d_in[0];
    float* out = (float*)d_out;
    int n_tiles = in_sizes[0] / TILE_FLOATS;   // 4096

    int grid = GRID < n_tiles ? GRID : n_tiles;
    cudaFuncSetAttribute(lif_kernel, cudaFuncAttributeMaxDynamicSharedMemorySize,
                         SMEM_BYTES);
    lif_kernel<<<grid, ROWS, SMEM_BYTES>>>(x, out, n_tiles);
}

// round 6
// speedup vs baseline: 1.0949x; 1.0867x over previous
#include <cuda_runtime.h>
#include <cstdint>

// LIF spike scan. x: [64, 8192, 100] fp32 (T contiguous) -> spikes (same shape).
//   mem = mem*TAU + x_t - w ; spike = (mem > THRESH)
//   w = BETA*w + (1-BETA)*(A*mem + B*spike) ; mem -= spike*THRESH
//
// R6: back to the R3 structure (independent CTAs, TMA bulk in/out, smem scan)
// but with 64-row tiles (25.6KB) so 8 CTAs fit per SM: 8 staggered
// load/compute/store phase machines per SM keep DRAM continuously fed.

#define TAU    0.5f
#define THRESH 0.5f
#define BETA   0.9f
#define C_MS   0.05f   // (1-BETA)*A == (1-BETA)*B

constexpr int T_LEN       = 100;
constexpr int ROWS        = 64;                  // rows/tile == threads/CTA
constexpr int TILE_FLOATS = ROWS * T_LEN;        // 6400
constexpr int TILE_BYTES  = TILE_FLOATS * 4;     // 25600
constexpr int DATA_OFF    = 16;                  // one mbarrier slot
constexpr int SMEM_BYTES  = DATA_OFF + TILE_BYTES;   // 25,616

__device__ __forceinline__ void lif_step(float xt, float& mem, float& w, float& sp) {
    mem = fmaf(mem, TAU, xt) - w;
    sp  = (mem > THRESH) ? 1.0f : 0.0f;
    w   = fmaf(BETA, w, fmaf(C_MS, mem, C_MS * sp));
    mem = fmaf(-sp, THRESH, mem);
}

__global__ __launch_bounds__(ROWS, 8) void lif_kernel(const float* __restrict__ x,
                                                      float* __restrict__ out) {
    extern __shared__ float smem[];
    const int tid = threadIdx.x;

    uint32_t sb;
    asm("{ .reg .u64 t; cvta.to.shared.u64 t, %1; cvt.u32.u64 %0, t; }"
        : "=r"(sb) : "l"(smem));
    const uint32_t mbar = sb;
    const uint32_t dsh  = sb + DATA_OFF;
    float* buf = smem + DATA_OFF / 4;

    const float* __restrict__ xin  = x   + (size_t)blockIdx.x * TILE_FLOATS;
    float* __restrict__       xout = out + (size_t)blockIdx.x * TILE_FLOATS;

    if (tid == 0) {
        asm volatile("mbarrier.init.shared.b64 [%0], 1;" :: "r"(mbar) : "memory");
        // fence.proxy covers init->TMA ordering within the same thread via
        // mbarrier.arrive.expect_tx below; no cross-thread visibility needed yet.
        asm volatile("mbarrier.arrive.expect_tx.shared.b64 _, [%0], %1;"
                     :: "r"(mbar), "r"((uint32_t)TILE_BYTES) : "memory");
        asm volatile("cp.async.bulk.shared::cta.global.mbarrier::complete_tx::bytes "
                     "[%0], [%1], %2, [%3];"
                     :: "r"(dsh), "l"(xin), "r"((uint32_t)TILE_BYTES),
                        "r"(mbar) : "memory");
    }
    __syncthreads();   // all threads see the initialized mbarrier

    // Wait for the load (parity 0).
    {
        uint32_t done;
        asm volatile(
            "{\n\t.reg .pred p;\n\t"
            "mbarrier.try_wait.parity.acquire.cta.shared::cta.b64 p, [%1], 0;\n\t"
            "selp.b32 %0, 1, 0, p;\n\t}"
            : "=r"(done) : "r"(mbar) : "memory");
        if (!done) {
            asm volatile(
                "{\n\t.reg .pred P1;\n\t"
                "WL_%=:\n\t"
                "mbarrier.try_wait.parity.acquire.cta.shared::cta.b64 P1, [%0], 0, 0x989680;\n\t"
                "@P1 bra.uni WD_%=;\n\t"
                "bra.uni WL_%=;\n\t"
                "WD_%=:\n\t}"
                :: "r"(mbar) : "memory");
        }
    }

    // Scan: one thread per row; float4 smem access is bank-conflict-free
    // (100 % 32 == 4: each quarter-warp phase covers all 32 banks once).
    {
        float4* srow = reinterpret_cast<float4*>(buf + tid * T_LEN);
        float mem = 0.0f, w = 0.0f;
        #pragma unroll
        for (int j = 0; j < T_LEN / 4; j++) {
            float4 v = srow[j];
            float4 sp;
            lif_step(v.x, mem, w, sp.x);
            lif_step(v.y, mem, w, sp.y);
            lif_step(v.z, mem, w, sp.z);
            lif_step(v.w, mem, w, sp.w);
            srow[j] = sp;
        }
    }
    __syncthreads();

    // Bulk store smem -> gmem; must drain before CTA exit.
    if (tid == 0) {
        asm volatile("fence.proxy.async.shared::cta;" ::: "memory");
        asm volatile("cp.async.bulk.global.shared::cta.bulk_group [%0], [%1], %2;"
                     :: "l"(xout), "r"(dsh), "r"((uint32_t)TILE_BYTES) : "memory");
        asm volatile("cp.async.bulk.commit_group;" ::: "memory");
        asm volatile("cp.async.bulk.wait_group 0;" ::: "memory");
    }
}

extern "C" void kernel_launch(void* const* d_in, const int* in_sizes, int n_in,
                              void* d_out, int out_size) {
    const float* x = (const float*)d_in[0];
    float* out = (float*)d_out;
    int grid = in_sizes[0] / TILE_FLOATS;      // 8192

    cudaFuncSetAttribute(lif_kernel, cudaFuncAttributeMaxDynamicSharedMemorySize,
                         SMEM_BYTES);
    lif_kernel<<<grid, ROWS, SMEM_BYTES>>>(x, out);
}